// round 13
// baseline (speedup 1.0000x reference)
#include <cuda_runtime.h>
#include <stdint.h>

// Fixed problem shapes
#define BQ 2
#define NQ 16384
#define SQ 4096
#define CQ 64
#define NS 32
#define OUTC 67
#define NCELL 1000            // 10x10x10 grid, cell = radius = 0.1
#define WARPS_B 8             // centers per query block
#define HB 64                 // wide hist/scatter blocks
#define NTILE 2048            // transpose tiles (512 n x 2 c x 2 b)
#define QBLOCKS (BQ * SQ / WARPS_B)   // 1024 query blocks
#define STP 17                // float4 row pitch in stage (conflict-free)
#define CPB (BQ * SQ / HB)    // centers per hist/scatter block = 128

// Device scratch (no allocations allowed). Count arrays start zero (static
// init) and are re-zeroed by k2 each replay -> stateless under graph replay.
__device__ float4 g_xyzp[BQ * NQ];                  // packed xyz, cell id in .w
__device__ float4 g_sorted[BQ * NQ];                // cell-sorted xyz, orig idx in .w
__device__ float4 g_cxyz[BQ * SQ];                  // packed centers, cell id in .w
__device__ float4 g_csorted[BQ * SQ];               // cell-sorted centers, orig s in .w
__device__ float  g_featT[(size_t)BQ * NQ * CQ];    // features [B,N,C]
__device__ int    g_cellcnt[BQ * NCELL];            // point histogram
__device__ int    g_cellstart[BQ * (NCELL + 1)];    // point exclusive prefix
__device__ int    g_cellfill[BQ * NCELL];           // point scatter cursors
__device__ int    g_ccnt[BQ * NCELL];               // center histogram
__device__ int    g_cfill[BQ * NCELL];              // center scatter cursors

__device__ __forceinline__ int cell_of(float v) {
    int c = (int)(v * 10.0f);
    return min(9, max(0, c));
}

// one 32x32 transpose tile of [B,C,N] -> [B,N,C]; id in [0, NTILE)
__device__ __forceinline__ void transpose_tile(const float* __restrict__ feat, int id) {
    __shared__ float tile[32][33];
    int n0 = (id & 511) * 32;
    int c0 = ((id >> 9) & 1) * 32;
    int b  = id >> 10;
    int tx = threadIdx.x & 31;
    int ty = threadIdx.x >> 5;                      // 0..7
#pragma unroll
    for (int j = 0; j < 32; j += 8)
        tile[ty + j][tx] = feat[((size_t)b * CQ + (c0 + ty + j)) * NQ + (n0 + tx)];
    __syncthreads();
#pragma unroll
    for (int j = 0; j < 32; j += 8)
        g_featT[((size_t)b * NQ + (n0 + ty + j)) * CQ + (c0 + tx)] = tile[tx][ty + j];
}

// ---------------------------------------------------------------------------
// K1: blocks 0..HB-1 = pack + histogram for points AND centers;
//     rest = ALL transpose tiles
// ---------------------------------------------------------------------------
__global__ __launch_bounds__(256)
void k1_hist(const float* __restrict__ xyz,
             const float* __restrict__ new_xyz,
             const float* __restrict__ feat) {
    if (blockIdx.x < HB) {
        int i = blockIdx.x * (BQ * NQ / HB) + threadIdx.x;
        int end = (blockIdx.x + 1) * (BQ * NQ / HB);
        for (; i < end; i += 256) {
            float x = xyz[3 * i + 0], y = xyz[3 * i + 1], z = xyz[3 * i + 2];
            int cell = (cell_of(z) * 10 + cell_of(y)) * 10 + cell_of(x);
            g_xyzp[i] = make_float4(x, y, z, __int_as_float(cell));
            atomicAdd(&g_cellcnt[(i >> 14) * NCELL + cell], 1);
        }
        if (threadIdx.x < CPB) {                    // centers: 128/block, guarded
            int j = blockIdx.x * CPB + threadIdx.x;
            float x = new_xyz[3 * j + 0], y = new_xyz[3 * j + 1], z = new_xyz[3 * j + 2];
            int cell = (cell_of(z) * 10 + cell_of(y)) * 10 + cell_of(x);
            g_cxyz[j] = make_float4(x, y, z, __int_as_float(cell));
            atomicAdd(&g_ccnt[(j >> 12) * NCELL + cell], 1);
        }
    } else {
        transpose_tile(feat, blockIdx.x - HB);
    }
}

// ---------------------------------------------------------------------------
// K2: 4 blocks. 0,1 = point-cell scan; 2,3 = center-cell scan. Re-zeroes.
// ---------------------------------------------------------------------------
__global__ __launch_bounds__(256)
void k2_scan() {
    __shared__ int wsum[8], wbase[8];
    const int which = blockIdx.x >> 1;
    const int b = blockIdx.x & 1;
    const int t = threadIdx.x;
    const int lane = t & 31, wid = t >> 5;

    int* cnt  = (which ? g_ccnt  : g_cellcnt) + b * NCELL;
    int* fill = (which ? g_cfill : g_cellfill) + b * NCELL;

    int cnt4[4];
    int own = 0;
    if (t < 250) {
#pragma unroll
        for (int j = 0; j < 4; j++) { cnt4[j] = cnt[4 * t + j]; own += cnt4[j]; }
    }
    int inc = own;
#pragma unroll
    for (int d = 1; d < 32; d <<= 1) {
        int v = __shfl_up_sync(0xffffffffu, inc, d);
        if (lane >= d) inc += v;
    }
    if (lane == 31) wsum[wid] = inc;
    __syncthreads();
    if (t == 0) {
        int run = 0;
#pragma unroll
        for (int w = 0; w < 8; w++) { wbase[w] = run; run += wsum[w]; }
    }
    __syncthreads();
    if (t < 250) {
        int run = wbase[wid] + inc - own;
#pragma unroll
        for (int j = 0; j < 4; j++) {
            int bin = 4 * t + j;
            if (which == 0) g_cellstart[b * (NCELL + 1) + bin] = run;
            fill[bin] = run;
            cnt[bin] = 0;
            run += cnt4[j];
        }
    }
    if (t == 0 && which == 0) g_cellstart[b * (NCELL + 1) + NCELL] = NQ;
}

// ---------------------------------------------------------------------------
// K3: scatter points and centers into cell order
// ---------------------------------------------------------------------------
__global__ __launch_bounds__(256)
void k3_scatter() {
    int i = blockIdx.x * (BQ * NQ / HB) + threadIdx.x;
    int end = (blockIdx.x + 1) * (BQ * NQ / HB);
    for (; i < end; i += 256) {
        float4 p = g_xyzp[i];
        int cell = __float_as_int(p.w);
        int b = i >> 14, n = i & (NQ - 1);
        int pos = atomicAdd(&g_cellfill[b * NCELL + cell], 1);
        g_sorted[b * NQ + pos] = make_float4(p.x, p.y, p.z, __int_as_float(n));
    }
    if (threadIdx.x < CPB) {
        int j = blockIdx.x * CPB + threadIdx.x;
        float4 p = g_cxyz[j];
        int cell = __float_as_int(p.w);
        int b = j >> 12, s = j & (SQ - 1);
        int pos = atomicAdd(&g_cfill[b * NCELL + cell], 1);
        g_csorted[b * SQ + pos] = make_float4(p.x, p.y, p.z, __int_as_float(s));
    }
}

// ---------------------------------------------------------------------------
// K4: fused ball query + grouping. Phase A per warp (2x-unrolled candidate
// loop, transposed bitmask). Phase B per warp-PAIR with named barriers —
// 4 independent chains instead of one block-wide serial chain.
// ---------------------------------------------------------------------------
__global__ __launch_bounds__(256)
void query_group_kernel(float* __restrict__ out) {
    __shared__ __align__(16) float4 stage[4][32 * STP];   // 34.8KB; masks alias this
    __shared__ int shidx[WARPS_B][NS];
    __shared__ int sh_s[WARPS_B];

    const int tid  = threadIdx.x;
    const int warp = tid >> 5;
    const int lane = tid & 31;
    const int csort = blockIdx.x * WARPS_B + warp;
    const int b = csort / SQ;
    const size_t chan_stride = (size_t)SQ * NS;

    // ---------------- Phase A: ball query ----------------
    {
        unsigned* mask = (unsigned*)stage + warp * (NQ / 32);   // 2KB/warp (16KB total)

        float4 cp = g_csorted[csort];
        const float cx = cp.x, cy = cp.y, cz = cp.z;
        const int   s  = __float_as_int(cp.w);
        const float r2 = (float)(0.1 * 0.1);
        if (lane == 0) sh_s[warp] = s;

        {
            uint4* m4 = (uint4*)mask;
#pragma unroll
            for (int i = lane; i < NQ / 128; i += 32) m4[i] = make_uint4(0, 0, 0, 0);
        }
        __syncwarp();

        const int x0 = max(0, (int)floorf((cx - 0.1f) * 10.0f - 0.002f));
        const int x1 = min(9, (int)floorf((cx + 0.1f) * 10.0f + 0.002f));
        const int y0 = max(0, (int)floorf((cy - 0.1f) * 10.0f - 0.002f));
        const int y1 = min(9, (int)floorf((cy + 0.1f) * 10.0f + 0.002f));
        const int z0 = max(0, (int)floorf((cz - 0.1f) * 10.0f - 0.002f));
        const int z1 = min(9, (int)floorf((cz + 0.1f) * 10.0f + 0.002f));

        const float4* __restrict__ srt = g_sorted + (size_t)b * NQ;
        const int* __restrict__ cs = g_cellstart + b * (NCELL + 1);

        for (int zc = z0; zc <= z1; zc++) {
            for (int yc = y0; yc <= y1; yc++) {
                int rowbase = (zc * 10 + yc) * 10;
                int st = cs[rowbase + x0];
                int en = cs[rowbase + x1 + 1];
                // 64 candidates/iter; both halves clamped (duplicate OR idempotent)
                for (int ibase = st; ibase < en; ibase += 64) {
                    int i0 = min(ibase + lane, en - 1);
                    int i1 = min(ibase + 32 + lane, en - 1);
                    float4 p0 = srt[i0];
                    float4 p1 = srt[i1];
                    float dx0 = __fadd_rn(cx, -p0.x);
                    float dy0 = __fadd_rn(cy, -p0.y);
                    float dz0 = __fadd_rn(cz, -p0.z);
                    float d20 = __fadd_rn(__fadd_rn(__fmul_rn(dx0, dx0), __fmul_rn(dy0, dy0)),
                                          __fmul_rn(dz0, dz0));
                    float dx1 = __fadd_rn(cx, -p1.x);
                    float dy1 = __fadd_rn(cy, -p1.y);
                    float dz1 = __fadd_rn(cz, -p1.z);
                    float d21 = __fadd_rn(__fadd_rn(__fmul_rn(dx1, dx1), __fmul_rn(dy1, dy1)),
                                          __fmul_rn(dz1, dz1));
                    int oi0 = __float_as_int(p0.w);
                    int oi1 = __float_as_int(p1.w);
                    int w0 = oi0 >> 5, w1 = oi1 >> 5;
                    unsigned* a0 = &mask[((w0 & 15) << 5) + (w0 >> 4)];
                    unsigned* a1 = &mask[((w1 & 15) << 5) + (w1 >> 4)];
                    if (d20 < r2) atomicOr(a0, 1u << (oi0 & 31));
                    if (d21 < r2) atomicOr(a1, 1u << (oi1 & 31));
                }
            }
        }
        __syncwarp();

        // conflict-free single-pass extraction (ascending original index)
        unsigned wreg[16];
        int pc = 0;
#pragma unroll
        for (int j = 0; j < 16; j++) {
            wreg[j] = mask[(j << 5) + lane];
            pc += __popc(wreg[j]);
        }
        int inc = pc;
#pragma unroll
        for (int d = 1; d < 32; d <<= 1) {
            int v = __shfl_up_sync(0xffffffffu, inc, d);
            if (lane >= d) inc += v;
        }
        const int cnt  = __shfl_sync(0xffffffffu, inc, 31);
        const int excl = inc - pc;
        if (pc > 0 && excl < NS) {
            int pos = excl;
            int basei = lane * 512;
#pragma unroll
            for (int j = 0; j < 16; j++) {
                unsigned w = wreg[j];
                while (w && pos < NS) {
                    int bpos = __ffs(w) - 1;
                    w &= w - 1;
                    shidx[warp][pos++] = basei + (j << 5) + bpos;
                }
            }
        }
        __syncwarp();

        int myidx = (cnt == 0) ? 0 : shidx[warp][(lane < cnt) ? lane : 0];
        __syncwarp();
        shidx[warp][lane] = myidx;

        // grouped_xyz channels 0..2
        float4 p = g_xyzp[(size_t)b * NQ + myidx];
        float* ob = out + ((size_t)b * OUTC * SQ + s) * NS + lane;
        __stcs(ob + 0 * chan_stride, __fadd_rn(p.x, -cx));
        __stcs(ob + 1 * chan_stride, __fadd_rn(p.y, -cy));
        __stcs(ob + 2 * chan_stride, __fadd_rn(p.z, -cz));
    }
    __syncthreads();   // masks dead; shidx + sh_s finalized for all warps

    // ---------------- Phase B: per-pair grouping with named barriers --------
    const int pair = warp >> 1;                     // 0..3
    const int wp   = warp & 1;                      // warp within pair
    const int pt   = tid & 63;                      // pair-local thread id
    const int g    = pt >> 4;                       // 0..3 (row group)
    const int l16  = pt & 15;                       // float4 column
    const int barid = pair + 1;                     // named barriers 1..4

    float4* stg = stage[pair];
    const float4* __restrict__ ft4 =
        (const float4*)(g_featT + (size_t)b * NQ * CQ);

#pragma unroll
    for (int i = 0; i < 2; i++) {
        const int c = pair * 2 + i;

        // stage 32 rows x 16 float4 (coalesced; 8-deep MLP per thread)
#pragma unroll
        for (int rr = 0; rr < 8; rr++) {
            int row = g * 8 + rr;
            stg[row * STP + l16] = __ldg(ft4 + (size_t)shidx[c][row] * 16 + l16);
        }
        asm volatile("bar.sync %0, 64;" :: "r"(barid) : "memory");

        // write channels 3..66: warp wp covers float4-groups {wp, wp+2, ...}
        const int sc = sh_s[c];
        float* ob = out + ((size_t)b * OUTC * SQ + sc) * NS + lane + 3 * chan_stride;
#pragma unroll
        for (int j = 0; j < 8; j++) {
            int cc = wp + j * 2;
            float4 v = stg[lane * STP + cc];
            float* o = ob + (size_t)(4 * cc) * chan_stride;
            __stcs(o + 0 * chan_stride, v.x);
            __stcs(o + 1 * chan_stride, v.y);
            __stcs(o + 2 * chan_stride, v.z);
            __stcs(o + 3 * chan_stride, v.w);
        }
        asm volatile("bar.sync %0, 64;" :: "r"(barid) : "memory");
    }
}

// ---------------------------------------------------------------------------
// Launch
// ---------------------------------------------------------------------------
extern "C" void kernel_launch(void* const* d_in, const int* in_sizes, int n_in,
                              void* d_out, int out_size) {
    const float* xyz     = (const float*)d_in[0];   // [B,N,3]
    const float* new_xyz = (const float*)d_in[1];   // [B,S,3]
    const float* feat    = (const float*)d_in[2];   // [B,C,N]
    float* out = (float*)d_out;                     // [B,67,S,NS]

    k1_hist<<<HB + NTILE, 256>>>(xyz, new_xyz, feat);
    k2_scan<<<2 * BQ, 256>>>();
    k3_scatter<<<HB, 256>>>();

    query_group_kernel<<<QBLOCKS, 256>>>(out);
}

// round 14
// speedup vs baseline: 1.1710x; 1.1710x over previous
#include <cuda_runtime.h>
#include <stdint.h>

// Fixed problem shapes
#define BQ 2
#define NQ 16384
#define SQ 4096
#define CQ 64
#define NS 32
#define OUTC 67
#define NCELL 1000            // 10x10x10 grid, cell = radius = 0.1
#define WARPS_B 8             // centers per query block
#define HB 64                 // wide hist/scatter blocks
#define NTILE 2048            // transpose tiles (512 n x 2 c x 2 b)
#define QBLOCKS (BQ * SQ / WARPS_B)   // 1024 query blocks
#define STP 17                // float4 row pitch in stage (conflict-free)
#define CPB (BQ * SQ / HB)    // centers per hist/scatter block = 128

// Device scratch (no allocations allowed). Count arrays start zero (static
// init) and are re-zeroed by k2 each replay -> stateless under graph replay.
__device__ float4 g_xyzp[BQ * NQ];                  // packed xyz, cell id in .w
__device__ float4 g_sorted[BQ * NQ];                // cell-sorted xyz, orig idx in .w
__device__ float4 g_cxyz[BQ * SQ];                  // packed centers, cell id in .w
__device__ float4 g_csorted[BQ * SQ];               // cell-sorted centers, orig s in .w
__device__ float  g_featT[(size_t)BQ * NQ * CQ];    // features [B,N,C]
__device__ int    g_cellcnt[BQ * NCELL];            // point histogram
__device__ int    g_cellstart[BQ * (NCELL + 1)];    // point exclusive prefix
__device__ int    g_cellfill[BQ * NCELL];           // point scatter cursors
__device__ int    g_ccnt[BQ * NCELL];               // center histogram
__device__ int    g_cfill[BQ * NCELL];              // center scatter cursors

__device__ __forceinline__ int cell_of(float v) {
    int c = (int)(v * 10.0f);
    return min(9, max(0, c));
}

// one 32x32 transpose tile of [B,C,N] -> [B,N,C]; id in [0, NTILE)
__device__ __forceinline__ void transpose_tile(const float* __restrict__ feat, int id) {
    __shared__ float tile[32][33];
    int n0 = (id & 511) * 32;
    int c0 = ((id >> 9) & 1) * 32;
    int b  = id >> 10;
    int tx = threadIdx.x & 31;
    int ty = threadIdx.x >> 5;                      // 0..7
#pragma unroll
    for (int j = 0; j < 32; j += 8)
        tile[ty + j][tx] = feat[((size_t)b * CQ + (c0 + ty + j)) * NQ + (n0 + tx)];
    __syncthreads();
#pragma unroll
    for (int j = 0; j < 32; j += 8)
        g_featT[((size_t)b * NQ + (n0 + ty + j)) * CQ + (c0 + tx)] = tile[tx][ty + j];
}

// ---------------------------------------------------------------------------
// K1: blocks 0..HB-1 = pack + histogram for points AND centers;
//     rest = ALL transpose tiles
// ---------------------------------------------------------------------------
__global__ __launch_bounds__(256)
void k1_hist(const float* __restrict__ xyz,
             const float* __restrict__ new_xyz,
             const float* __restrict__ feat) {
    if (blockIdx.x < HB) {
        int i = blockIdx.x * (BQ * NQ / HB) + threadIdx.x;
        int end = (blockIdx.x + 1) * (BQ * NQ / HB);
        for (; i < end; i += 256) {
            float x = xyz[3 * i + 0], y = xyz[3 * i + 1], z = xyz[3 * i + 2];
            int cell = (cell_of(z) * 10 + cell_of(y)) * 10 + cell_of(x);
            g_xyzp[i] = make_float4(x, y, z, __int_as_float(cell));
            atomicAdd(&g_cellcnt[(i >> 14) * NCELL + cell], 1);
        }
        if (threadIdx.x < CPB) {                    // centers: 128/block, guarded
            int j = blockIdx.x * CPB + threadIdx.x;
            float x = new_xyz[3 * j + 0], y = new_xyz[3 * j + 1], z = new_xyz[3 * j + 2];
            int cell = (cell_of(z) * 10 + cell_of(y)) * 10 + cell_of(x);
            g_cxyz[j] = make_float4(x, y, z, __int_as_float(cell));
            atomicAdd(&g_ccnt[(j >> 12) * NCELL + cell], 1);
        }
    } else {
        transpose_tile(feat, blockIdx.x - HB);
    }
}

// ---------------------------------------------------------------------------
// K2: 4 blocks. 0,1 = point-cell scan; 2,3 = center-cell scan. Re-zeroes.
// ---------------------------------------------------------------------------
__global__ __launch_bounds__(256)
void k2_scan() {
    __shared__ int wsum[8], wbase[8];
    const int which = blockIdx.x >> 1;
    const int b = blockIdx.x & 1;
    const int t = threadIdx.x;
    const int lane = t & 31, wid = t >> 5;

    int* cnt  = (which ? g_ccnt  : g_cellcnt) + b * NCELL;
    int* fill = (which ? g_cfill : g_cellfill) + b * NCELL;

    int cnt4[4];
    int own = 0;
    if (t < 250) {
#pragma unroll
        for (int j = 0; j < 4; j++) { cnt4[j] = cnt[4 * t + j]; own += cnt4[j]; }
    }
    int inc = own;
#pragma unroll
    for (int d = 1; d < 32; d <<= 1) {
        int v = __shfl_up_sync(0xffffffffu, inc, d);
        if (lane >= d) inc += v;
    }
    if (lane == 31) wsum[wid] = inc;
    __syncthreads();
    if (t == 0) {
        int run = 0;
#pragma unroll
        for (int w = 0; w < 8; w++) { wbase[w] = run; run += wsum[w]; }
    }
    __syncthreads();
    if (t < 250) {
        int run = wbase[wid] + inc - own;
#pragma unroll
        for (int j = 0; j < 4; j++) {
            int bin = 4 * t + j;
            if (which == 0) g_cellstart[b * (NCELL + 1) + bin] = run;
            fill[bin] = run;
            cnt[bin] = 0;
            run += cnt4[j];
        }
    }
    if (t == 0 && which == 0) g_cellstart[b * (NCELL + 1) + NCELL] = NQ;
}

// ---------------------------------------------------------------------------
// K3: scatter points and centers into cell order
// ---------------------------------------------------------------------------
__global__ __launch_bounds__(256)
void k3_scatter() {
    int i = blockIdx.x * (BQ * NQ / HB) + threadIdx.x;
    int end = (blockIdx.x + 1) * (BQ * NQ / HB);
    for (; i < end; i += 256) {
        float4 p = g_xyzp[i];
        int cell = __float_as_int(p.w);
        int b = i >> 14, n = i & (NQ - 1);
        int pos = atomicAdd(&g_cellfill[b * NCELL + cell], 1);
        g_sorted[b * NQ + pos] = make_float4(p.x, p.y, p.z, __int_as_float(n));
    }
    if (threadIdx.x < CPB) {
        int j = blockIdx.x * CPB + threadIdx.x;
        float4 p = g_cxyz[j];
        int cell = __float_as_int(p.w);
        int b = j >> 12, s = j & (SQ - 1);
        int pos = atomicAdd(&g_cfill[b * NCELL + cell], 1);
        g_csorted[b * SQ + pos] = make_float4(p.x, p.y, p.z, __int_as_float(s));
    }
}

// ---------------------------------------------------------------------------
// K4: fused ball query + grouping.
// Phase A per warp: 2x-unrolled candidate loop, transposed bitmask,
//   conflict-free single-pass extraction.
// Phase B block-cooperative: ping-pong double-buffered staging, ONE
//   block-wide barrier per center (trailing barrier provably redundant).
// ---------------------------------------------------------------------------
__global__ __launch_bounds__(256)
void query_group_kernel(float* __restrict__ out) {
    __shared__ __align__(16) float4 stage[2][32 * STP];   // 17.4KB; masks alias
    __shared__ int shidx[WARPS_B][NS];
    __shared__ int sh_s[WARPS_B];

    const int tid  = threadIdx.x;
    const int warp = tid >> 5;
    const int lane = tid & 31;
    const int csort = blockIdx.x * WARPS_B + warp;
    const int b = csort / SQ;
    const size_t chan_stride = (size_t)SQ * NS;

    // ---------------- Phase A: ball query ----------------
    {
        unsigned* mask = (unsigned*)stage + warp * (NQ / 32);   // 2KB/warp

        float4 cp = g_csorted[csort];
        const float cx = cp.x, cy = cp.y, cz = cp.z;
        const int   s  = __float_as_int(cp.w);
        const float r2 = (float)(0.1 * 0.1);
        if (lane == 0) sh_s[warp] = s;

        {
            uint4* m4 = (uint4*)mask;
#pragma unroll
            for (int i = lane; i < NQ / 128; i += 32) m4[i] = make_uint4(0, 0, 0, 0);
        }
        __syncwarp();

        const int x0 = max(0, (int)floorf((cx - 0.1f) * 10.0f - 0.002f));
        const int x1 = min(9, (int)floorf((cx + 0.1f) * 10.0f + 0.002f));
        const int y0 = max(0, (int)floorf((cy - 0.1f) * 10.0f - 0.002f));
        const int y1 = min(9, (int)floorf((cy + 0.1f) * 10.0f + 0.002f));
        const int z0 = max(0, (int)floorf((cz - 0.1f) * 10.0f - 0.002f));
        const int z1 = min(9, (int)floorf((cz + 0.1f) * 10.0f + 0.002f));

        const float4* __restrict__ srt = g_sorted + (size_t)b * NQ;
        const int* __restrict__ cs = g_cellstart + b * (NCELL + 1);

        for (int zc = z0; zc <= z1; zc++) {
            for (int yc = y0; yc <= y1; yc++) {
                int rowbase = (zc * 10 + yc) * 10;
                int st = cs[rowbase + x0];
                int en = cs[rowbase + x1 + 1];
                // 64 candidates/iter; both halves clamped (duplicate OR idempotent)
                for (int ibase = st; ibase < en; ibase += 64) {
                    int i0 = min(ibase + lane, en - 1);
                    int i1 = min(ibase + 32 + lane, en - 1);
                    float4 p0 = srt[i0];
                    float4 p1 = srt[i1];
                    float dx0 = __fadd_rn(cx, -p0.x);
                    float dy0 = __fadd_rn(cy, -p0.y);
                    float dz0 = __fadd_rn(cz, -p0.z);
                    float d20 = __fadd_rn(__fadd_rn(__fmul_rn(dx0, dx0), __fmul_rn(dy0, dy0)),
                                          __fmul_rn(dz0, dz0));
                    float dx1 = __fadd_rn(cx, -p1.x);
                    float dy1 = __fadd_rn(cy, -p1.y);
                    float dz1 = __fadd_rn(cz, -p1.z);
                    float d21 = __fadd_rn(__fadd_rn(__fmul_rn(dx1, dx1), __fmul_rn(dy1, dy1)),
                                          __fmul_rn(dz1, dz1));
                    int oi0 = __float_as_int(p0.w);
                    int oi1 = __float_as_int(p1.w);
                    int w0 = oi0 >> 5, w1 = oi1 >> 5;
                    unsigned* a0 = &mask[((w0 & 15) << 5) + (w0 >> 4)];
                    unsigned* a1 = &mask[((w1 & 15) << 5) + (w1 >> 4)];
                    if (d20 < r2) atomicOr(a0, 1u << (oi0 & 31));
                    if (d21 < r2) atomicOr(a1, 1u << (oi1 & 31));
                }
            }
        }
        __syncwarp();

        // conflict-free single-pass extraction (ascending original index)
        unsigned wreg[16];
        int pc = 0;
#pragma unroll
        for (int j = 0; j < 16; j++) {
            wreg[j] = mask[(j << 5) + lane];
            pc += __popc(wreg[j]);
        }
        int inc = pc;
#pragma unroll
        for (int d = 1; d < 32; d <<= 1) {
            int v = __shfl_up_sync(0xffffffffu, inc, d);
            if (lane >= d) inc += v;
        }
        const int cnt  = __shfl_sync(0xffffffffu, inc, 31);
        const int excl = inc - pc;
        if (pc > 0 && excl < NS) {
            int pos = excl;
            int basei = lane * 512;
#pragma unroll
            for (int j = 0; j < 16; j++) {
                unsigned w = wreg[j];
                while (w && pos < NS) {
                    int bpos = __ffs(w) - 1;
                    w &= w - 1;
                    shidx[warp][pos++] = basei + (j << 5) + bpos;
                }
            }
        }
        __syncwarp();

        int myidx = (cnt == 0) ? 0 : shidx[warp][(lane < cnt) ? lane : 0];
        __syncwarp();
        shidx[warp][lane] = myidx;

        // grouped_xyz channels 0..2 (coalesced over lane=k)
        float4 p = g_xyzp[(size_t)b * NQ + myidx];
        float* ob = out + ((size_t)b * OUTC * SQ + s) * NS + lane;
        __stcs(ob + 0 * chan_stride, __fadd_rn(p.x, -cx));
        __stcs(ob + 1 * chan_stride, __fadd_rn(p.y, -cy));
        __stcs(ob + 2 * chan_stride, __fadd_rn(p.z, -cz));
    }
    __syncthreads();   // masks dead; shidx + sh_s finalized for all warps

    // ---------------- Phase B: ping-pong double-buffered grouping ----------
    const int r  = tid >> 4;                        // 0..15
    const int c4 = tid & 15;                        // 0..15
    const int k  = tid & 31;
    const int w  = tid >> 5;                        // 0..7

    const float4* __restrict__ ft4 =
        (const float4*)(g_featT + (size_t)b * NQ * CQ);

    float4 v0 = __ldg(ft4 + (size_t)shidx[0][r]      * 16 + c4);
    float4 v1 = __ldg(ft4 + (size_t)shidx[0][r + 16] * 16 + c4);

#pragma unroll 1
    for (int c = 0; c < WARPS_B; c++) {
        float4* stg = stage[c & 1];
        stg[r * STP + c4]        = v0;
        stg[(r + 16) * STP + c4] = v1;
        __syncthreads();                            // only barrier per center

        if (c + 1 < WARPS_B) {                      // prefetch next center
            v0 = __ldg(ft4 + (size_t)shidx[c + 1][r]      * 16 + c4);
            v1 = __ldg(ft4 + (size_t)shidx[c + 1][r + 16] * 16 + c4);
        }

        // write channels 3..66: lane=k coalesced 128B stores
        const int sc = sh_s[c];
        float* ob = out + ((size_t)b * OUTC * SQ + sc) * NS + k + 3 * chan_stride;
#pragma unroll
        for (int cc = w; cc < 16; cc += 8) {
            float4 v = stg[k * STP + cc];
            float* o = ob + (size_t)(4 * cc) * chan_stride;
            __stcs(o + 0 * chan_stride, v.x);
            __stcs(o + 1 * chan_stride, v.y);
            __stcs(o + 2 * chan_stride, v.z);
            __stcs(o + 3 * chan_stride, v.w);
        }
        // no trailing barrier: next center writes the OTHER buffer; reuse of
        // this buffer at c+2 is ordered by the c+1 barrier.
    }
}

// ---------------------------------------------------------------------------
// Launch
// ---------------------------------------------------------------------------
extern "C" void kernel_launch(void* const* d_in, const int* in_sizes, int n_in,
                              void* d_out, int out_size) {
    const float* xyz     = (const float*)d_in[0];   // [B,N,3]
    const float* new_xyz = (const float*)d_in[1];   // [B,S,3]
    const float* feat    = (const float*)d_in[2];   // [B,C,N]
    float* out = (float*)d_out;                     // [B,67,S,NS]

    k1_hist<<<HB + NTILE, 256>>>(xyz, new_xyz, feat);
    k2_scan<<<2 * BQ, 256>>>();
    k3_scatter<<<HB, 256>>>();

    query_group_kernel<<<QBLOCKS, 256>>>(out);
}